// round 4
// baseline (speedup 1.0000x reference)
#include <cuda_runtime.h>
#include <cuda_bf16.h>

// ---------------------------------------------------------------------------
// MultiLayerGnn: 3-layer GCN (+linear skips) + global_sort_pool top-K
// N=50000, E=800000, F_IN=H=64, C_OUT=32, K=1024
// edge_index delivered by the harness as int32 (2 rows of E).
// ---------------------------------------------------------------------------

#define NMAX 50000
#define EMAX 800000
#define KTOP 1024

static constexpr size_t AL(size_t x) { return (x + 255) & ~size_t(255); }

static constexpr size_t OFF_HW   = 0;
static constexpr size_t OFF_ACCA = AL(OFF_HW   + (size_t)NMAX * 64 * 4);
static constexpr size_t OFF_ACCB = AL(OFF_ACCA + (size_t)NMAX * 64 * 4);
static constexpr size_t OFF_DINV = AL(OFF_ACCB + (size_t)NMAX * 64 * 4);
static constexpr size_t OFF_DEG  = AL(OFF_DINV + (size_t)NMAX * 4);
static constexpr size_t OFF_FILL = AL(OFF_DEG  + (size_t)NMAX * 4);
static constexpr size_t OFF_RP   = AL(OFF_FILL + (size_t)NMAX * 4);
static constexpr size_t OFF_CSRS = AL(OFF_RP   + (size_t)(NMAX + 1) * 4);
static constexpr size_t OFF_CSRN = AL(OFF_CSRS + (size_t)EMAX * 4);
static constexpr size_t OFF_SKEY = AL(OFF_CSRN + (size_t)EMAX * 4);
static constexpr size_t OFF_H1   = AL(OFF_SKEY + (size_t)NMAX * 4);
static constexpr size_t OFF_H2   = AL(OFF_H1   + 4096 * 4);
static constexpr size_t OFF_CAND = AL(OFF_H2   + 4096 * 4);
static constexpr size_t OFF_MISC = AL(OFF_CAND + 4096 * 8);
static constexpr size_t SCRATCH_TOTAL = AL(OFF_MISC + 256);

__device__ __align__(256) unsigned char g_scratch[SCRATCH_TOTAL];

// ---------------------------------------------------------------------------
// Prep kernels
// ---------------------------------------------------------------------------

__global__ void init_kernel(int* deg, int* fill, int* hist1, int* hist2,
                            int* misc, int n) {
    int i = blockIdx.x * blockDim.x + threadIdx.x;
    if (i < n) { deg[i] = 1; fill[i] = 0; }   // deg starts at 1 (self-loop)
    if (i < 4096) { hist1[i] = 0; hist2[i] = 0; }
    if (i == 0) { misc[0] = 0; }              // candidate count
}

__global__ void deg_kernel(const int* __restrict__ ei, int e,
                           int* __restrict__ deg, int n) {
    int i = blockIdx.x * blockDim.x + threadIdx.x;
    if (i >= e) return;
    unsigned d = (unsigned)ei[e + i];
    if (d < (unsigned)n) atomicAdd(&deg[d], 1);
}

__global__ void dinv_kernel(const int* __restrict__ deg,
                            float* __restrict__ dinv, int n) {
    int i = blockIdx.x * blockDim.x + threadIdx.x;
    if (i >= n) return;
    dinv[i] = rsqrtf((float)deg[i]);
}

// One-block exclusive scan of (deg[i]-1) -> rowptr
__global__ void scan_kernel(const int* __restrict__ deg,
                            int* __restrict__ rowptr, int n) {
    __shared__ int ssum[1024];
    int tid = threadIdx.x;
    int C = (n + 1023) / 1024;
    int begin = tid * C;
    int end = begin + C; if (end > n) end = n;
    int s = 0;
    for (int i = begin; i < end; i++) s += deg[i] - 1;
    ssum[tid] = s;
    __syncthreads();
    for (int off = 1; off < 1024; off <<= 1) {
        int v = (tid >= off) ? ssum[tid - off] : 0;
        __syncthreads();
        ssum[tid] += v;
        __syncthreads();
    }
    int run = (tid == 0) ? 0 : ssum[tid - 1];
    for (int i = begin; i < end; i++) {
        rowptr[i] = run;
        run += deg[i] - 1;
    }
    if (tid == 1023) rowptr[n] = ssum[1023];
}

__global__ void scatter_kernel(const int* __restrict__ ei, int e,
                               const float* __restrict__ dinv,
                               const int* __restrict__ rowptr,
                               int* __restrict__ fill,
                               int* __restrict__ csrsrc,
                               float* __restrict__ csrnorm, int n) {
    int i = blockIdx.x * blockDim.x + threadIdx.x;
    if (i >= e) return;
    unsigned s = (unsigned)ei[i];
    unsigned d = (unsigned)ei[e + i];
    if (s >= (unsigned)n || d >= (unsigned)n) return;
    int p = atomicAdd(&fill[d], 1);
    int idx = rowptr[d] + p;
    csrsrc[idx] = (int)s;
    csrnorm[idx] = dinv[s] * dinv[d];
}

// ---------------------------------------------------------------------------
// Fused GEMM: hw = h @ W   and (skip layers) accout = b + 0.5*(h@Wl + bl)
// Block: 64 rows x CW cols, 128 threads, each thread 8 x (CW/16) outputs.
// ---------------------------------------------------------------------------

template <int CW, bool SKIP>
__global__ __launch_bounds__(128) void gemm_fused(
    const float* __restrict__ hin,
    const float* __restrict__ W, const float* __restrict__ Wl,
    const float* __restrict__ b, const float* __restrict__ bl,
    float* __restrict__ hw, float* __restrict__ accout, int n) {
    constexpr int HOUT = SKIP ? CW / 2 : CW;
    constexpr int CT = CW / 16;
    __shared__ float As[64][64];
    __shared__ float Ws[64][CW];

    int tid = threadIdx.x;
    int base = blockIdx.x * 64;

    // Load A tile (64x64) via float4
    for (int f = tid; f < 64 * 16; f += 128) {
        int row = f >> 4, c4 = f & 15;
        float4 v = make_float4(0.f, 0.f, 0.f, 0.f);
        int gr = base + row;
        if (gr < n) v = ((const float4*)hin)[(size_t)gr * 16 + c4];
        ((float4*)&As[row][0])[c4] = v;
    }
    // Load weights
    for (int f = tid; f < 64 * CW; f += 128) {
        int k = f / CW, j = f % CW;
        float w;
        if (SKIP) w = (j < HOUT) ? W[k * HOUT + j] : Wl[k * HOUT + (j - HOUT)];
        else      w = W[k * CW + j];
        Ws[k][j] = w;
    }
    __syncthreads();

    int tcol = tid & 15, trow = tid >> 4;
    float acc[8][CT];
#pragma unroll
    for (int i = 0; i < 8; i++)
#pragma unroll
        for (int c = 0; c < CT; c++) acc[i][c] = 0.f;

#pragma unroll 4
    for (int k = 0; k < 64; k++) {
        float a[8];
#pragma unroll
        for (int i = 0; i < 8; i++) a[i] = As[trow * 8 + i][k];
        float w[CT];
#pragma unroll
        for (int c = 0; c < CT; c++) w[c] = Ws[k][tcol * CT + c];
#pragma unroll
        for (int i = 0; i < 8; i++)
#pragma unroll
            for (int c = 0; c < CT; c++)
                acc[i][c] = fmaf(a[i], w[c], acc[i][c]);
    }

#pragma unroll
    for (int i = 0; i < 8; i++) {
        int gr = base + trow * 8 + i;
        if (gr >= n) continue;
#pragma unroll
        for (int c = 0; c < CT; c++) {
            int col = tcol * CT + c;
            if (SKIP) {
                if (col < HOUT) {
                    hw[(size_t)gr * HOUT + col] = acc[i][c];
                } else {
                    int j = col - HOUT;
                    accout[(size_t)gr * HOUT + j] = b[j] + 0.5f * (acc[i][c] + bl[j]);
                }
            } else {
                hw[(size_t)gr * CW + col] = acc[i][c];
            }
        }
    }
}

// ---------------------------------------------------------------------------
// Aggregation: warp per node, CSR gather.  out = relu(accin + dinv^2*hw[i] + sum)
// ---------------------------------------------------------------------------

__global__ void agg64(const float* __restrict__ hw, const float* accin,
                      const float* __restrict__ dinv,
                      const int* __restrict__ rowptr,
                      const int* __restrict__ csrsrc,
                      const float* __restrict__ csrnorm,
                      float* out, int n) {
    int warp = (blockIdx.x * blockDim.x + threadIdx.x) >> 5;
    int lane = threadIdx.x & 31;
    if (warp >= n) return;
    const float2* hp = (const float2*)hw;
    float di = dinv[warp];
    float di2 = di * di;
    float2 s2 = hp[(size_t)warp * 32 + lane];
    float ax = s2.x * di2, ay = s2.y * di2;
    int e = rowptr[warp], e1 = rowptr[warp + 1];
    for (; e + 1 < e1; e += 2) {
        int sa = csrsrc[e];     float na = csrnorm[e];
        int sb = csrsrc[e + 1]; float nb = csrnorm[e + 1];
        float2 va = hp[(size_t)sa * 32 + lane];
        float2 vb = hp[(size_t)sb * 32 + lane];
        ax = fmaf(va.x, na, ax); ay = fmaf(va.y, na, ay);
        ax = fmaf(vb.x, nb, ax); ay = fmaf(vb.y, nb, ay);
    }
    if (e < e1) {
        int sa = csrsrc[e]; float na = csrnorm[e];
        float2 va = hp[(size_t)sa * 32 + lane];
        ax = fmaf(va.x, na, ax); ay = fmaf(va.y, na, ay);
    }
    float2 bse = ((const float2*)accin)[(size_t)warp * 32 + lane];
    float rx = fmaxf(bse.x + ax, 0.f);
    float ry = fmaxf(bse.y + ay, 0.f);
    ((float2*)out)[(size_t)warp * 32 + lane] = make_float2(rx, ry);
}

__global__ void agg32(const float* __restrict__ hw, const float* __restrict__ bias,
                      const float* __restrict__ dinv,
                      const int* __restrict__ rowptr,
                      const int* __restrict__ csrsrc,
                      const float* __restrict__ csrnorm,
                      float* __restrict__ out, int n) {
    int warp = (blockIdx.x * blockDim.x + threadIdx.x) >> 5;
    int lane = threadIdx.x & 31;
    if (warp >= n) return;
    float di = dinv[warp];
    float di2 = di * di;
    float acc = hw[(size_t)warp * 32 + lane] * di2;
    int e = rowptr[warp], e1 = rowptr[warp + 1];
    for (; e + 1 < e1; e += 2) {
        int sa = csrsrc[e];     float na = csrnorm[e];
        int sb = csrsrc[e + 1]; float nb = csrnorm[e + 1];
        acc = fmaf(hw[(size_t)sa * 32 + lane], na, acc);
        acc = fmaf(hw[(size_t)sb * 32 + lane], nb, acc);
    }
    if (e < e1) {
        acc = fmaf(hw[(size_t)csrsrc[e] * 32 + lane], csrnorm[e], acc);
    }
    out[(size_t)warp * 32 + lane] = acc + bias[lane];
}

// ---------------------------------------------------------------------------
// Top-K selection (two-level 12-bit histogram threshold + bitonic sort)
// Key: sortable uint32 of h3[:,31] (descending), ties -> lower idx first.
// ---------------------------------------------------------------------------

__global__ void key_kernel(const float* __restrict__ h3, int n,
                           unsigned* __restrict__ skey, int* __restrict__ hist1) {
    int i = blockIdx.x * blockDim.x + threadIdx.x;
    if (i >= n) return;
    unsigned u = __float_as_uint(h3[(size_t)i * 32 + 31]);
    unsigned s = (u & 0x80000000u) ? ~u : (u | 0x80000000u);
    skey[i] = s;
    atomicAdd(&hist1[s >> 20], 1);
}

__global__ void findbin1(const int* __restrict__ hist1, int* B, int* cA, int need) {
    int cum = 0;
    for (int b = 4095; b >= 0; --b) {
        cum += hist1[b];
        if (cum >= need) { *B = b; *cA = cum - hist1[b]; return; }
    }
    *B = 0; *cA = 0;
}

__global__ void hist2_kernel(const unsigned* __restrict__ skey, int n,
                             const int* __restrict__ B, int* __restrict__ hist2) {
    int i = blockIdx.x * blockDim.x + threadIdx.x;
    if (i >= n) return;
    unsigned s = skey[i];
    if ((int)(s >> 20) == *B) atomicAdd(&hist2[(s >> 8) & 0xFFF], 1);
}

__global__ void findbin2(const int* __restrict__ hist2, const int* B,
                         const int* cA, unsigned* T, int need) {
    int cum = *cA;
    for (int b = 4095; b >= 0; --b) {
        cum += hist2[b];
        if (cum >= need) {
            *T = (((unsigned)*B) << 20) | (((unsigned)b) << 8);
            return;
        }
    }
    *T = ((unsigned)*B) << 20;
}

__global__ void compact_kernel(const unsigned* __restrict__ skey, int n,
                               const unsigned* __restrict__ T,
                               unsigned long long* __restrict__ cand,
                               int* __restrict__ cnt) {
    int i = blockIdx.x * blockDim.x + threadIdx.x;
    if (i >= n) return;
    unsigned s = skey[i];
    if (s >= *T) {
        int p = atomicAdd(cnt, 1);
        if (p < 4096)
            cand[p] = (((unsigned long long)s) << 32) |
                      (unsigned long long)(0xFFFFFFFFu - (unsigned)i);
    }
}

__global__ void sortout_kernel(const unsigned long long* __restrict__ cand,
                               const int* __restrict__ cnt,
                               const float* __restrict__ h3,
                               float* __restrict__ out) {
    __shared__ unsigned long long sd[4096];
    int tid = threadIdx.x;  // 1024 threads
    int C = *cnt; if (C > 4096) C = 4096;
    for (int i = tid; i < 4096; i += 1024) sd[i] = (i < C) ? cand[i] : 0ull;
    __syncthreads();
    for (int k = 2; k <= 4096; k <<= 1) {
        for (int j = k >> 1; j > 0; j >>= 1) {
            for (int t = tid; t < 4096; t += 1024) {
                int ixj = t ^ j;
                if (ixj > t) {
                    bool up = ((t & k) == 0);  // descending region
                    unsigned long long A = sd[t], Bv = sd[ixj];
                    bool sw = up ? (A < Bv) : (A > Bv);
                    if (sw) { sd[t] = Bv; sd[ixj] = A; }
                }
            }
            __syncthreads();
        }
    }
    for (int t = tid; t < KTOP * 32; t += 1024) {
        int r = t >> 5, c = t & 31;
        unsigned idx = 0xFFFFFFFFu - (unsigned)(sd[r] & 0xFFFFFFFFull);
        out[t] = h3[(size_t)idx * 32 + c];
    }
}

// ---------------------------------------------------------------------------
// Launch
// ---------------------------------------------------------------------------

extern "C" void kernel_launch(void* const* d_in, const int* in_sizes, int n_in,
                              void* d_out, int out_size) {
    const float* x   = (const float*)d_in[0];
    const float* W1  = (const float*)d_in[1];
    const float* b1  = (const float*)d_in[2];
    const float* Wl1 = (const float*)d_in[3];
    const float* bl1 = (const float*)d_in[4];
    const float* W2  = (const float*)d_in[5];
    const float* b2  = (const float*)d_in[6];
    const float* Wl2 = (const float*)d_in[7];
    const float* bl2 = (const float*)d_in[8];
    const float* W3  = (const float*)d_in[9];
    const float* b3  = (const float*)d_in[10];
    const int*   ei  = (const int*)d_in[11];   // int32 per harness dtype map

    int n = in_sizes[0] / 64;
    int e = in_sizes[11] / 2;

    unsigned char* base = nullptr;
    cudaGetSymbolAddress((void**)&base, g_scratch);

    float* hw      = (float*)(base + OFF_HW);
    float* accA    = (float*)(base + OFF_ACCA);
    float* accB    = (float*)(base + OFF_ACCB);
    float* dinv    = (float*)(base + OFF_DINV);
    int*   deg     = (int*)(base + OFF_DEG);
    int*   fill    = (int*)(base + OFF_FILL);
    int*   rowptr  = (int*)(base + OFF_RP);
    int*   csrsrc  = (int*)(base + OFF_CSRS);
    float* csrnorm = (float*)(base + OFF_CSRN);
    unsigned* skey = (unsigned*)(base + OFF_SKEY);
    int*   hist1   = (int*)(base + OFF_H1);
    int*   hist2   = (int*)(base + OFF_H2);
    unsigned long long* cand = (unsigned long long*)(base + OFF_CAND);
    int*   misc    = (int*)(base + OFF_MISC);
    int*   cnt     = misc + 0;
    int*   Bbin    = misc + 1;
    int*   cA      = misc + 2;
    unsigned* T    = (unsigned*)(misc + 3);

    int ninit = (n > 4096) ? n : 4096;

    init_kernel<<<(ninit + 255) / 256, 256>>>(deg, fill, hist1, hist2, misc, n);
    deg_kernel<<<(e + 255) / 256, 256>>>(ei, e, deg, n);
    dinv_kernel<<<(n + 255) / 256, 256>>>(deg, dinv, n);
    scan_kernel<<<1, 1024>>>(deg, rowptr, n);
    scatter_kernel<<<(e + 255) / 256, 256>>>(ei, e, dinv, rowptr, fill, csrsrc, csrnorm, n);

    int gblocks = (n + 63) / 64;
    int ablocks = (n + 7) / 8;

    // Layer 1
    gemm_fused<128, true><<<gblocks, 128>>>(x, W1, Wl1, b1, bl1, hw, accA, n);
    agg64<<<ablocks, 256>>>(hw, accA, dinv, rowptr, csrsrc, csrnorm, accA, n);
    // Layer 2
    gemm_fused<128, true><<<gblocks, 128>>>(accA, W2, Wl2, b2, bl2, hw, accB, n);
    agg64<<<ablocks, 256>>>(hw, accB, dinv, rowptr, csrsrc, csrnorm, accB, n);
    // Layer 3 (no skip, 32 channels)
    gemm_fused<32, false><<<gblocks, 128>>>(accB, W3, nullptr, nullptr, nullptr, hw, nullptr, n);
    agg32<<<ablocks, 256>>>(hw, b3, dinv, rowptr, csrsrc, csrnorm, accA, n);

    // Top-K selection + ordered output
    key_kernel<<<(n + 255) / 256, 256>>>(accA, n, skey, hist1);
    findbin1<<<1, 1>>>(hist1, Bbin, cA, KTOP);
    hist2_kernel<<<(n + 255) / 256, 256>>>(skey, n, Bbin, hist2);
    findbin2<<<1, 1>>>(hist2, Bbin, cA, T, KTOP);
    compact_kernel<<<(n + 255) / 256, 256>>>(skey, n, T, cand, cnt);
    sortout_kernel<<<1, 1024>>>(cand, cnt, accA, (float*)d_out);
}

// round 6
// speedup vs baseline: 1.1066x; 1.1066x over previous
#include <cuda_runtime.h>
#include <cuda_bf16.h>

// ---------------------------------------------------------------------------
// MultiLayerGnn: 3-layer GCN (+linear skips) + global_sort_pool top-K
// N=50000, E=800000, F_IN=H=64, C_OUT=32, K=1024
// edge_index delivered by the harness as int32 (2 rows of E).
// ---------------------------------------------------------------------------

#define NMAX 50000
#define EMAX 800000
#define KTOP 1024

static constexpr size_t AL(size_t x) { return (x + 255) & ~size_t(255); }

static constexpr size_t OFF_HW   = 0;
static constexpr size_t OFF_ACCA = AL(OFF_HW   + (size_t)NMAX * 64 * 4);
static constexpr size_t OFF_ACCB = AL(OFF_ACCA + (size_t)NMAX * 64 * 4);
static constexpr size_t OFF_DINV = AL(OFF_ACCB + (size_t)NMAX * 64 * 4);
static constexpr size_t OFF_DEG  = AL(OFF_DINV + (size_t)NMAX * 4);
static constexpr size_t OFF_FILL = AL(OFF_DEG  + (size_t)NMAX * 4);
static constexpr size_t OFF_RP   = AL(OFF_FILL + (size_t)NMAX * 4);
static constexpr size_t OFF_CSRS = AL(OFF_RP   + (size_t)(NMAX + 1) * 4);
static constexpr size_t OFF_CSRN = AL(OFF_CSRS + (size_t)EMAX * 4);
static constexpr size_t OFF_SKEY = AL(OFF_CSRN + (size_t)EMAX * 4);
static constexpr size_t OFF_H1   = AL(OFF_SKEY + (size_t)NMAX * 4);
static constexpr size_t OFF_H2   = AL(OFF_H1   + 4096 * 4);
static constexpr size_t OFF_CAND = AL(OFF_H2   + 4096 * 4);
static constexpr size_t OFF_BSUM = AL(OFF_CAND + 4096 * 8);
static constexpr size_t OFF_BPRE = AL(OFF_BSUM + 256 * 4);
static constexpr size_t OFF_MISC = AL(OFF_BPRE + 256 * 4);
static constexpr size_t SCRATCH_TOTAL = AL(OFF_MISC + 256);

__device__ __align__(256) unsigned char g_scratch[SCRATCH_TOTAL];

// ---------------------------------------------------------------------------
// Prep kernels
// ---------------------------------------------------------------------------

__global__ void init_kernel(int* deg, int* fill, int* hist1, int* hist2,
                            int* misc, int n) {
    int i = blockIdx.x * blockDim.x + threadIdx.x;
    if (i < n) { deg[i] = 1; fill[i] = 0; }   // deg starts at 1 (self-loop)
    if (i < 4096) { hist1[i] = 0; hist2[i] = 0; }
    if (i == 0) { misc[0] = 0; }              // candidate count
}

__global__ void deg_kernel(const int* __restrict__ ei, int e,
                           int* __restrict__ deg, int n) {
    int i = blockIdx.x * blockDim.x + threadIdx.x;
    if (i >= e) return;
    unsigned d = (unsigned)ei[e + i];
    if (d < (unsigned)n) atomicAdd(&deg[d], 1);
}

// Phase A: per-block sums of (deg-1) + fused dinv computation
__global__ void scanA(const int* __restrict__ deg, float* __restrict__ dinv,
                      int* __restrict__ bsum, int n) {
    __shared__ int sh[256];
    int t = threadIdx.x;
    int i = blockIdx.x * 256 + t;
    int v = 0;
    if (i < n) {
        int d = deg[i];
        dinv[i] = rsqrtf((float)d);
        v = d - 1;
    }
    sh[t] = v;
    __syncthreads();
    for (int off = 128; off > 0; off >>= 1) {
        if (t < off) sh[t] += sh[t + off];
        __syncthreads();
    }
    if (t == 0) bsum[blockIdx.x] = sh[0];
}

// Phase B: 1-block exclusive scan of 256 block sums; writes rowptr[n]=total
__global__ void scanB(const int* __restrict__ bsum, int* __restrict__ bpre,
                      int* __restrict__ rowptr, int nb, int n) {
    __shared__ int sh[256];
    int t = threadIdx.x;
    int v = (t < nb) ? bsum[t] : 0;
    sh[t] = v;
    __syncthreads();
    for (int off = 1; off < 256; off <<= 1) {
        int x = (t >= off) ? sh[t - off] : 0;
        __syncthreads();
        sh[t] += x;
        __syncthreads();
    }
    bpre[t] = sh[t] - v;               // exclusive prefix
    if (t == 255) rowptr[n] = sh[255]; // total
}

// Phase C: local exclusive scan + block prefix -> rowptr
__global__ void scanC(const int* __restrict__ deg, const int* __restrict__ bpre,
                      int* __restrict__ rowptr, int n) {
    __shared__ int sh[256];
    int t = threadIdx.x;
    int i = blockIdx.x * 256 + t;
    int v = (i < n) ? deg[i] - 1 : 0;
    sh[t] = v;
    __syncthreads();
    for (int off = 1; off < 256; off <<= 1) {
        int x = (t >= off) ? sh[t - off] : 0;
        __syncthreads();
        sh[t] += x;
        __syncthreads();
    }
    if (i < n) rowptr[i] = bpre[blockIdx.x] + sh[t] - v;
}

__global__ void scatter_kernel(const int* __restrict__ ei, int e,
                               const float* __restrict__ dinv,
                               const int* __restrict__ rowptr,
                               int* __restrict__ fill,
                               int* __restrict__ csrsrc,
                               float* __restrict__ csrnorm, int n) {
    int i = blockIdx.x * blockDim.x + threadIdx.x;
    if (i >= e) return;
    unsigned s = (unsigned)ei[i];
    unsigned d = (unsigned)ei[e + i];
    if (s >= (unsigned)n || d >= (unsigned)n) return;
    int p = atomicAdd(&fill[d], 1);
    int idx = rowptr[d] + p;
    csrsrc[idx] = (int)s;
    csrnorm[idx] = dinv[s] * dinv[d];
}

// ---------------------------------------------------------------------------
// Fused GEMM: hw = h @ W   and (skip layers) accout = b + 0.5*(h@Wl + bl)
// ---------------------------------------------------------------------------

template <int CW, bool SKIP>
__global__ __launch_bounds__(128) void gemm_fused(
    const float* __restrict__ hin,
    const float* __restrict__ W, const float* __restrict__ Wl,
    const float* __restrict__ b, const float* __restrict__ bl,
    float* __restrict__ hw, float* __restrict__ accout, int n) {
    constexpr int HOUT = SKIP ? CW / 2 : CW;
    constexpr int CT = CW / 16;
    __shared__ float As[64][64];
    __shared__ float Ws[64][CW];

    int tid = threadIdx.x;
    int base = blockIdx.x * 64;

    for (int f = tid; f < 64 * 16; f += 128) {
        int row = f >> 4, c4 = f & 15;
        float4 v = make_float4(0.f, 0.f, 0.f, 0.f);
        int gr = base + row;
        if (gr < n) v = ((const float4*)hin)[(size_t)gr * 16 + c4];
        ((float4*)&As[row][0])[c4] = v;
    }
    for (int f = tid; f < 64 * CW; f += 128) {
        int k = f / CW, j = f % CW;
        float w;
        if (SKIP) w = (j < HOUT) ? W[k * HOUT + j] : Wl[k * HOUT + (j - HOUT)];
        else      w = W[k * CW + j];
        Ws[k][j] = w;
    }
    __syncthreads();

    int tcol = tid & 15, trow = tid >> 4;
    float acc[8][CT];
#pragma unroll
    for (int i = 0; i < 8; i++)
#pragma unroll
        for (int c = 0; c < CT; c++) acc[i][c] = 0.f;

#pragma unroll 4
    for (int k = 0; k < 64; k++) {
        float a[8];
#pragma unroll
        for (int i = 0; i < 8; i++) a[i] = As[trow * 8 + i][k];
        float w[CT];
#pragma unroll
        for (int c = 0; c < CT; c++) w[c] = Ws[k][tcol * CT + c];
#pragma unroll
        for (int i = 0; i < 8; i++)
#pragma unroll
            for (int c = 0; c < CT; c++)
                acc[i][c] = fmaf(a[i], w[c], acc[i][c]);
    }

#pragma unroll
    for (int i = 0; i < 8; i++) {
        int gr = base + trow * 8 + i;
        if (gr >= n) continue;
#pragma unroll
        for (int c = 0; c < CT; c++) {
            int col = tcol * CT + c;
            if (SKIP) {
                if (col < HOUT) {
                    hw[(size_t)gr * HOUT + col] = acc[i][c];
                } else {
                    int j = col - HOUT;
                    accout[(size_t)gr * HOUT + j] = b[j] + 0.5f * (acc[i][c] + bl[j]);
                }
            } else {
                hw[(size_t)gr * CW + col] = acc[i][c];
            }
        }
    }
}

// ---------------------------------------------------------------------------
// Aggregation: warp per node, CSR gather, 4x unrolled for MLP.
// ---------------------------------------------------------------------------

__global__ void agg64(const float* __restrict__ hw, const float* accin,
                      const float* __restrict__ dinv,
                      const int* __restrict__ rowptr,
                      const int* __restrict__ csrsrc,
                      const float* __restrict__ csrnorm,
                      float* out, int n) {
    int warp = (blockIdx.x * blockDim.x + threadIdx.x) >> 5;
    int lane = threadIdx.x & 31;
    if (warp >= n) return;
    const float2* hp = (const float2*)hw;
    float di = dinv[warp];
    float di2 = di * di;
    float2 s2 = hp[(size_t)warp * 32 + lane];
    float ax = s2.x * di2, ay = s2.y * di2;
    int e = rowptr[warp], e1 = rowptr[warp + 1];
    for (; e + 3 < e1; e += 4) {
        int s0 = csrsrc[e],      s1 = csrsrc[e + 1];
        int s2i = csrsrc[e + 2], s3 = csrsrc[e + 3];
        float n0 = csrnorm[e],     n1 = csrnorm[e + 1];
        float n2 = csrnorm[e + 2], n3 = csrnorm[e + 3];
        float2 v0 = hp[(size_t)s0 * 32 + lane];
        float2 v1 = hp[(size_t)s1 * 32 + lane];
        float2 v2 = hp[(size_t)s2i * 32 + lane];
        float2 v3 = hp[(size_t)s3 * 32 + lane];
        ax = fmaf(v0.x, n0, ax); ay = fmaf(v0.y, n0, ay);
        ax = fmaf(v1.x, n1, ax); ay = fmaf(v1.y, n1, ay);
        ax = fmaf(v2.x, n2, ax); ay = fmaf(v2.y, n2, ay);
        ax = fmaf(v3.x, n3, ax); ay = fmaf(v3.y, n3, ay);
    }
    for (; e < e1; e++) {
        int sa = csrsrc[e]; float na = csrnorm[e];
        float2 va = hp[(size_t)sa * 32 + lane];
        ax = fmaf(va.x, na, ax); ay = fmaf(va.y, na, ay);
    }
    float2 bse = ((const float2*)accin)[(size_t)warp * 32 + lane];
    float rx = fmaxf(bse.x + ax, 0.f);
    float ry = fmaxf(bse.y + ay, 0.f);
    ((float2*)out)[(size_t)warp * 32 + lane] = make_float2(rx, ry);
}

__global__ void agg32(const float* __restrict__ hw, const float* __restrict__ bias,
                      const float* __restrict__ dinv,
                      const int* __restrict__ rowptr,
                      const int* __restrict__ csrsrc,
                      const float* __restrict__ csrnorm,
                      float* __restrict__ out, int n) {
    int warp = (blockIdx.x * blockDim.x + threadIdx.x) >> 5;
    int lane = threadIdx.x & 31;
    if (warp >= n) return;
    float di = dinv[warp];
    float di2 = di * di;
    float acc = hw[(size_t)warp * 32 + lane] * di2;
    int e = rowptr[warp], e1 = rowptr[warp + 1];
    for (; e + 3 < e1; e += 4) {
        int s0 = csrsrc[e],     s1 = csrsrc[e + 1];
        int s2 = csrsrc[e + 2], s3 = csrsrc[e + 3];
        float n0 = csrnorm[e],     n1 = csrnorm[e + 1];
        float n2 = csrnorm[e + 2], n3 = csrnorm[e + 3];
        float v0 = hw[(size_t)s0 * 32 + lane];
        float v1 = hw[(size_t)s1 * 32 + lane];
        float v2 = hw[(size_t)s2 * 32 + lane];
        float v3 = hw[(size_t)s3 * 32 + lane];
        acc = fmaf(v0, n0, acc); acc = fmaf(v1, n1, acc);
        acc = fmaf(v2, n2, acc); acc = fmaf(v3, n3, acc);
    }
    for (; e < e1; e++) {
        acc = fmaf(hw[(size_t)csrsrc[e] * 32 + lane], csrnorm[e], acc);
    }
    out[(size_t)warp * 32 + lane] = acc + bias[lane];
}

// ---------------------------------------------------------------------------
// Top-K selection (round-4 proven path: sequential bin finders)
// Key: sortable uint32 of h3[:,31] (descending), ties -> lower idx first.
// ---------------------------------------------------------------------------

__global__ void key_kernel(const float* __restrict__ h3, int n,
                           unsigned* __restrict__ skey, int* __restrict__ hist1) {
    int i = blockIdx.x * blockDim.x + threadIdx.x;
    if (i >= n) return;
    unsigned u = __float_as_uint(h3[(size_t)i * 32 + 31]);
    unsigned s = (u & 0x80000000u) ? ~u : (u | 0x80000000u);
    skey[i] = s;
    atomicAdd(&hist1[s >> 20], 1);
}

__global__ void findbin1(const int* __restrict__ hist1, int* B, int* cA, int need) {
    int cum = 0;
    for (int b = 4095; b >= 0; --b) {
        cum += hist1[b];
        if (cum >= need) { *B = b; *cA = cum - hist1[b]; return; }
    }
    *B = 0; *cA = 0;
}

__global__ void hist2_kernel(const unsigned* __restrict__ skey, int n,
                             const int* __restrict__ B, int* __restrict__ hist2) {
    int i = blockIdx.x * blockDim.x + threadIdx.x;
    if (i >= n) return;
    unsigned s = skey[i];
    if ((int)(s >> 20) == *B) atomicAdd(&hist2[(s >> 8) & 0xFFF], 1);
}

__global__ void findbin2(const int* __restrict__ hist2, const int* B,
                         const int* cA, unsigned* T, int need) {
    int cum = *cA;
    for (int b = 4095; b >= 0; --b) {
        cum += hist2[b];
        if (cum >= need) {
            *T = (((unsigned)*B) << 20) | (((unsigned)b) << 8);
            return;
        }
    }
    *T = ((unsigned)*B) << 20;
}

__global__ void compact_kernel(const unsigned* __restrict__ skey, int n,
                               const unsigned* __restrict__ T,
                               unsigned long long* __restrict__ cand,
                               int* __restrict__ cnt) {
    int i = blockIdx.x * blockDim.x + threadIdx.x;
    if (i >= n) return;
    unsigned s = skey[i];
    if (s >= *T) {
        int p = atomicAdd(cnt, 1);
        if (p < 4096)
            cand[p] = (((unsigned long long)s) << 32) |
                      (unsigned long long)(0xFFFFFFFFu - (unsigned)i);
    }
}

__global__ void sortout_kernel(const unsigned long long* __restrict__ cand,
                               const int* __restrict__ cnt,
                               const float* __restrict__ h3,
                               float* __restrict__ out) {
    __shared__ unsigned long long sd[4096];
    int tid = threadIdx.x;  // 1024 threads
    int C = *cnt; if (C > 4096) C = 4096;
    for (int i = tid; i < 4096; i += 1024) sd[i] = (i < C) ? cand[i] : 0ull;
    __syncthreads();
    for (int k = 2; k <= 4096; k <<= 1) {
        for (int j = k >> 1; j > 0; j >>= 1) {
            for (int t = tid; t < 4096; t += 1024) {
                int ixj = t ^ j;
                if (ixj > t) {
                    bool up = ((t & k) == 0);  // descending region
                    unsigned long long A = sd[t], Bv = sd[ixj];
                    bool sw = up ? (A < Bv) : (A > Bv);
                    if (sw) { sd[t] = Bv; sd[ixj] = A; }
                }
            }
            __syncthreads();
        }
    }
    for (int t = tid; t < KTOP * 32; t += 1024) {
        int r = t >> 5, c = t & 31;
        unsigned idx = 0xFFFFFFFFu - (unsigned)(sd[r] & 0xFFFFFFFFull);
        out[t] = h3[(size_t)idx * 32 + c];
    }
}

// ---------------------------------------------------------------------------
// Launch
// ---------------------------------------------------------------------------

extern "C" void kernel_launch(void* const* d_in, const int* in_sizes, int n_in,
                              void* d_out, int out_size) {
    const float* x   = (const float*)d_in[0];
    const float* W1  = (const float*)d_in[1];
    const float* b1  = (const float*)d_in[2];
    const float* Wl1 = (const float*)d_in[3];
    const float* bl1 = (const float*)d_in[4];
    const float* W2  = (const float*)d_in[5];
    const float* b2  = (const float*)d_in[6];
    const float* Wl2 = (const float*)d_in[7];
    const float* bl2 = (const float*)d_in[8];
    const float* W3  = (const float*)d_in[9];
    const float* b3  = (const float*)d_in[10];
    const int*   ei  = (const int*)d_in[11];   // int32 per harness dtype map

    int n = in_sizes[0] / 64;
    int e = in_sizes[11] / 2;

    unsigned char* base = nullptr;
    cudaGetSymbolAddress((void**)&base, g_scratch);

    float* hw      = (float*)(base + OFF_HW);
    float* accA    = (float*)(base + OFF_ACCA);
    float* accB    = (float*)(base + OFF_ACCB);
    float* dinv    = (float*)(base + OFF_DINV);
    int*   deg     = (int*)(base + OFF_DEG);
    int*   fill    = (int*)(base + OFF_FILL);
    int*   rowptr  = (int*)(base + OFF_RP);
    int*   csrsrc  = (int*)(base + OFF_CSRS);
    float* csrnorm = (float*)(base + OFF_CSRN);
    unsigned* skey = (unsigned*)(base + OFF_SKEY);
    int*   hist1   = (int*)(base + OFF_H1);
    int*   hist2   = (int*)(base + OFF_H2);
    unsigned long long* cand = (unsigned long long*)(base + OFF_CAND);
    int*   bsum    = (int*)(base + OFF_BSUM);
    int*   bpre    = (int*)(base + OFF_BPRE);
    int*   misc    = (int*)(base + OFF_MISC);
    int*   cnt     = misc + 0;
    int*   Bbin    = misc + 1;
    int*   cA      = misc + 2;
    unsigned* T    = (unsigned*)(misc + 3);

    int ninit = (n > 4096) ? n : 4096;
    int nb = (n + 255) / 256;

    init_kernel<<<(ninit + 255) / 256, 256>>>(deg, fill, hist1, hist2, misc, n);
    deg_kernel<<<(e + 255) / 256, 256>>>(ei, e, deg, n);
    scanA<<<nb, 256>>>(deg, dinv, bsum, n);
    scanB<<<1, 256>>>(bsum, bpre, rowptr, nb, n);
    scanC<<<nb, 256>>>(deg, bpre, rowptr, n);
    scatter_kernel<<<(e + 255) / 256, 256>>>(ei, e, dinv, rowptr, fill, csrsrc, csrnorm, n);

    int gblocks = (n + 63) / 64;
    int ablocks = (n + 7) / 8;

    // Layer 1
    gemm_fused<128, true><<<gblocks, 128>>>(x, W1, Wl1, b1, bl1, hw, accA, n);
    agg64<<<ablocks, 256>>>(hw, accA, dinv, rowptr, csrsrc, csrnorm, accA, n);
    // Layer 2
    gemm_fused<128, true><<<gblocks, 128>>>(accA, W2, Wl2, b2, bl2, hw, accB, n);
    agg64<<<ablocks, 256>>>(hw, accB, dinv, rowptr, csrsrc, csrnorm, accB, n);
    // Layer 3 (no skip, 32 channels)
    gemm_fused<32, false><<<gblocks, 128>>>(accB, W3, nullptr, nullptr, nullptr, hw, nullptr, n);
    agg32<<<ablocks, 256>>>(hw, b3, dinv, rowptr, csrsrc, csrnorm, accA, n);

    // Top-K selection + ordered output (round-4 proven path)
    key_kernel<<<(n + 255) / 256, 256>>>(accA, n, skey, hist1);
    findbin1<<<1, 1>>>(hist1, Bbin, cA, KTOP);
    hist2_kernel<<<(n + 255) / 256, 256>>>(skey, n, Bbin, hist2);
    findbin2<<<1, 1>>>(hist2, Bbin, cA, T, KTOP);
    compact_kernel<<<(n + 255) / 256, 256>>>(skey, n, T, cand, cnt);
    sortout_kernel<<<1, 1024>>>(cand, cnt, accA, (float*)d_out);
}

// round 7
// speedup vs baseline: 1.6631x; 1.5030x over previous
#include <cuda_runtime.h>
#include <cuda_bf16.h>

// ---------------------------------------------------------------------------
// MultiLayerGnn: 3-layer GCN (+linear skips) + global_sort_pool top-K
// N=50000, E=800000, F_IN=H=64, C_OUT=32, K=1024
// edge_index delivered by the harness as int32 (2 rows of E).
// ---------------------------------------------------------------------------

#define NMAX 50000
#define EMAX 800000
#define KTOP 1024

static constexpr size_t AL(size_t x) { return (x + 255) & ~size_t(255); }

static constexpr size_t OFF_HW   = 0;
static constexpr size_t OFF_ACCA = AL(OFF_HW   + (size_t)NMAX * 64 * 4);
static constexpr size_t OFF_ACCB = AL(OFF_ACCA + (size_t)NMAX * 64 * 4);
static constexpr size_t OFF_DINV = AL(OFF_ACCB + (size_t)NMAX * 64 * 4);
static constexpr size_t OFF_DEG  = AL(OFF_DINV + (size_t)NMAX * 4);
static constexpr size_t OFF_FILL = AL(OFF_DEG  + (size_t)NMAX * 4);
static constexpr size_t OFF_RP   = AL(OFF_FILL + (size_t)NMAX * 4);
static constexpr size_t OFF_CSRS = AL(OFF_RP   + (size_t)(NMAX + 1) * 4);
static constexpr size_t OFF_CSRN = AL(OFF_CSRS + (size_t)EMAX * 4);
static constexpr size_t OFF_SKEY = AL(OFF_CSRN + (size_t)EMAX * 4);
static constexpr size_t OFF_H1   = AL(OFF_SKEY + (size_t)NMAX * 4);
static constexpr size_t OFF_H2   = AL(OFF_H1   + 4096 * 4);
static constexpr size_t OFF_CAND = AL(OFF_H2   + 4096 * 4);
static constexpr size_t OFF_BSUM = AL(OFF_CAND + 4096 * 8);
static constexpr size_t OFF_BPRE = AL(OFF_BSUM + 256 * 4);
static constexpr size_t OFF_MISC = AL(OFF_BPRE + 256 * 4);
static constexpr size_t SCRATCH_TOTAL = AL(OFF_MISC + 256);

__device__ __align__(256) unsigned char g_scratch[SCRATCH_TOTAL];

// ---------------------------------------------------------------------------
// Prep kernels
// ---------------------------------------------------------------------------

__global__ void init_kernel(int* deg, int* fill, int* hist1, int* hist2,
                            int* misc, int n) {
    int i = blockIdx.x * blockDim.x + threadIdx.x;
    if (i < n) { deg[i] = 1; fill[i] = 0; }   // deg starts at 1 (self-loop)
    if (i < 4096) { hist1[i] = 0; hist2[i] = 0; }
    if (i == 0) { misc[0] = 0; }              // candidate count
}

__global__ void deg_kernel(const int* __restrict__ ei, int e,
                           int* __restrict__ deg, int n) {
    int i = blockIdx.x * blockDim.x + threadIdx.x;
    if (i >= e) return;
    unsigned d = (unsigned)ei[e + i];
    if (d < (unsigned)n) atomicAdd(&deg[d], 1);
}

// Phase A: per-block sums of (deg-1) + fused dinv computation
__global__ void scanA(const int* __restrict__ deg, float* __restrict__ dinv,
                      int* __restrict__ bsum, int n) {
    __shared__ int sh[256];
    int t = threadIdx.x;
    int i = blockIdx.x * 256 + t;
    int v = 0;
    if (i < n) {
        int d = deg[i];
        dinv[i] = rsqrtf((float)d);
        v = d - 1;
    }
    sh[t] = v;
    __syncthreads();
    for (int off = 128; off > 0; off >>= 1) {
        if (t < off) sh[t] += sh[t + off];
        __syncthreads();
    }
    if (t == 0) bsum[blockIdx.x] = sh[0];
}

// Phase B: 1-block exclusive scan of 256 block sums; writes rowptr[n]=total
__global__ void scanB(const int* __restrict__ bsum, int* __restrict__ bpre,
                      int* __restrict__ rowptr, int nb, int n) {
    __shared__ int sh[256];
    int t = threadIdx.x;
    int v = (t < nb) ? bsum[t] : 0;
    sh[t] = v;
    __syncthreads();
    for (int off = 1; off < 256; off <<= 1) {
        int x = (t >= off) ? sh[t - off] : 0;
        __syncthreads();
        sh[t] += x;
        __syncthreads();
    }
    bpre[t] = sh[t] - v;               // exclusive prefix
    if (t == 255) rowptr[n] = sh[255]; // total
}

// Phase C: local exclusive scan + block prefix -> rowptr
__global__ void scanC(const int* __restrict__ deg, const int* __restrict__ bpre,
                      int* __restrict__ rowptr, int n) {
    __shared__ int sh[256];
    int t = threadIdx.x;
    int i = blockIdx.x * 256 + t;
    int v = (i < n) ? deg[i] - 1 : 0;
    sh[t] = v;
    __syncthreads();
    for (int off = 1; off < 256; off <<= 1) {
        int x = (t >= off) ? sh[t - off] : 0;
        __syncthreads();
        sh[t] += x;
        __syncthreads();
    }
    if (i < n) rowptr[i] = bpre[blockIdx.x] + sh[t] - v;
}

__global__ void scatter_kernel(const int* __restrict__ ei, int e,
                               const float* __restrict__ dinv,
                               const int* __restrict__ rowptr,
                               int* __restrict__ fill,
                               int* __restrict__ csrsrc,
                               float* __restrict__ csrnorm, int n) {
    int i = blockIdx.x * blockDim.x + threadIdx.x;
    if (i >= e) return;
    unsigned s = (unsigned)ei[i];
    unsigned d = (unsigned)ei[e + i];
    if (s >= (unsigned)n || d >= (unsigned)n) return;
    int p = atomicAdd(&fill[d], 1);
    int idx = rowptr[d] + p;
    csrsrc[idx] = (int)s;
    csrnorm[idx] = dinv[s] * dinv[d];
}

// ---------------------------------------------------------------------------
// Fused GEMM: hw = h @ W   and (skip layers) accout = b + 0.5*(h@Wl + bl)
// As stored transposed (As[k][row]) so the 8 row-values per k are 2 LDS.128.
// ---------------------------------------------------------------------------

template <int CW, bool SKIP>
__global__ __launch_bounds__(128) void gemm_fused(
    const float* __restrict__ hin,
    const float* __restrict__ W, const float* __restrict__ Wl,
    const float* __restrict__ b, const float* __restrict__ bl,
    float* __restrict__ hw, float* __restrict__ accout, int n) {
    constexpr int HOUT = SKIP ? CW / 2 : CW;
    constexpr int CT = CW / 16;
    __shared__ float As[64][64];   // As[k][row] (transposed)
    __shared__ float Ws[64][CW];

    int tid = threadIdx.x;
    int base = blockIdx.x * 64;

    for (int f = tid; f < 64 * 16; f += 128) {
        int row = f >> 4, c4 = f & 15;
        float4 v = make_float4(0.f, 0.f, 0.f, 0.f);
        int gr = base + row;
        if (gr < n) v = ((const float4*)hin)[(size_t)gr * 16 + c4];
        int k = c4 * 4;
        As[k + 0][row] = v.x;
        As[k + 1][row] = v.y;
        As[k + 2][row] = v.z;
        As[k + 3][row] = v.w;
    }
    for (int f = tid; f < 64 * CW; f += 128) {
        int k = f / CW, j = f % CW;
        float w;
        if (SKIP) w = (j < HOUT) ? W[k * HOUT + j] : Wl[k * HOUT + (j - HOUT)];
        else      w = W[k * CW + j];
        Ws[k][j] = w;
    }
    __syncthreads();

    int tcol = tid & 15, trow = tid >> 4;
    float acc[8][CT];
#pragma unroll
    for (int i = 0; i < 8; i++)
#pragma unroll
        for (int c = 0; c < CT; c++) acc[i][c] = 0.f;

#pragma unroll 4
    for (int k = 0; k < 64; k++) {
        float4 a0 = *(const float4*)&As[k][trow * 8];
        float4 a1 = *(const float4*)&As[k][trow * 8 + 4];
        float a[8] = {a0.x, a0.y, a0.z, a0.w, a1.x, a1.y, a1.z, a1.w};
        float w[CT];
#pragma unroll
        for (int c = 0; c < CT; c++) w[c] = Ws[k][tcol * CT + c];
#pragma unroll
        for (int i = 0; i < 8; i++)
#pragma unroll
            for (int c = 0; c < CT; c++)
                acc[i][c] = fmaf(a[i], w[c], acc[i][c]);
    }

#pragma unroll
    for (int i = 0; i < 8; i++) {
        int gr = base + trow * 8 + i;
        if (gr >= n) continue;
#pragma unroll
        for (int c = 0; c < CT; c++) {
            int col = tcol * CT + c;
            if (SKIP) {
                if (col < HOUT) {
                    hw[(size_t)gr * HOUT + col] = acc[i][c];
                } else {
                    int j = col - HOUT;
                    accout[(size_t)gr * HOUT + j] = b[j] + 0.5f * (acc[i][c] + bl[j]);
                }
            } else {
                hw[(size_t)gr * CW + col] = acc[i][c];
            }
        }
    }
}

// ---------------------------------------------------------------------------
// Aggregation: warp per node, CSR gather.
// ---------------------------------------------------------------------------

__global__ void agg64(const float* __restrict__ hw, const float* accin,
                      const float* __restrict__ dinv,
                      const int* __restrict__ rowptr,
                      const int* __restrict__ csrsrc,
                      const float* __restrict__ csrnorm,
                      float* out, int n) {
    int warp = (blockIdx.x * blockDim.x + threadIdx.x) >> 5;
    int lane = threadIdx.x & 31;
    if (warp >= n) return;
    const float2* hp = (const float2*)hw;
    float di = dinv[warp];
    float di2 = di * di;
    float2 s2 = hp[(size_t)warp * 32 + lane];
    float ax = s2.x * di2, ay = s2.y * di2;
    int e = rowptr[warp], e1 = rowptr[warp + 1];
    for (; e + 3 < e1; e += 4) {
        int s0 = csrsrc[e],      s1 = csrsrc[e + 1];
        int s2i = csrsrc[e + 2], s3 = csrsrc[e + 3];
        float n0 = csrnorm[e],     n1 = csrnorm[e + 1];
        float n2 = csrnorm[e + 2], n3 = csrnorm[e + 3];
        float2 v0 = hp[(size_t)s0 * 32 + lane];
        float2 v1 = hp[(size_t)s1 * 32 + lane];
        float2 v2 = hp[(size_t)s2i * 32 + lane];
        float2 v3 = hp[(size_t)s3 * 32 + lane];
        ax = fmaf(v0.x, n0, ax); ay = fmaf(v0.y, n0, ay);
        ax = fmaf(v1.x, n1, ax); ay = fmaf(v1.y, n1, ay);
        ax = fmaf(v2.x, n2, ax); ay = fmaf(v2.y, n2, ay);
        ax = fmaf(v3.x, n3, ax); ay = fmaf(v3.y, n3, ay);
    }
    for (; e < e1; e++) {
        int sa = csrsrc[e]; float na = csrnorm[e];
        float2 va = hp[(size_t)sa * 32 + lane];
        ax = fmaf(va.x, na, ax); ay = fmaf(va.y, na, ay);
    }
    float2 bse = ((const float2*)accin)[(size_t)warp * 32 + lane];
    float rx = fmaxf(bse.x + ax, 0.f);
    float ry = fmaxf(bse.y + ay, 0.f);
    ((float2*)out)[(size_t)warp * 32 + lane] = make_float2(rx, ry);
}

// Layer-3 agg (32 ch) with fused sort-key + hist1 build (lane 31 owns ch 31).
__global__ void agg32_key(const float* __restrict__ hw, const float* __restrict__ bias,
                          const float* __restrict__ dinv,
                          const int* __restrict__ rowptr,
                          const int* __restrict__ csrsrc,
                          const float* __restrict__ csrnorm,
                          float* __restrict__ out, int n,
                          unsigned* __restrict__ skey, int* __restrict__ hist1) {
    int warp = (blockIdx.x * blockDim.x + threadIdx.x) >> 5;
    int lane = threadIdx.x & 31;
    if (warp >= n) return;
    float di = dinv[warp];
    float di2 = di * di;
    float acc = hw[(size_t)warp * 32 + lane] * di2;
    int e = rowptr[warp], e1 = rowptr[warp + 1];
    for (; e + 3 < e1; e += 4) {
        int s0 = csrsrc[e],     s1 = csrsrc[e + 1];
        int s2 = csrsrc[e + 2], s3 = csrsrc[e + 3];
        float n0 = csrnorm[e],     n1 = csrnorm[e + 1];
        float n2 = csrnorm[e + 2], n3 = csrnorm[e + 3];
        float v0 = hw[(size_t)s0 * 32 + lane];
        float v1 = hw[(size_t)s1 * 32 + lane];
        float v2 = hw[(size_t)s2 * 32 + lane];
        float v3 = hw[(size_t)s3 * 32 + lane];
        acc = fmaf(v0, n0, acc); acc = fmaf(v1, n1, acc);
        acc = fmaf(v2, n2, acc); acc = fmaf(v3, n3, acc);
    }
    for (; e < e1; e++) {
        acc = fmaf(hw[(size_t)csrsrc[e] * 32 + lane], csrnorm[e], acc);
    }
    float v = acc + bias[lane];
    out[(size_t)warp * 32 + lane] = v;
    if (lane == 31) {
        unsigned u = __float_as_uint(v);
        unsigned s = (u & 0x80000000u) ? ~u : (u | 0x80000000u);
        skey[warp] = s;
        atomicAdd(&hist1[s >> 20], 1);
    }
}

// ---------------------------------------------------------------------------
// Top-K selection: warp-parallel bin finders (exact serial semantics)
// ---------------------------------------------------------------------------

// One warp. Lane l owns descending chunk of 128 bins: [4095-128l .. 4095-128l-127].
// Returns (B, cum) identical to the serial descending walk.
__device__ __forceinline__ void findbin_warp(const int* __restrict__ hist,
                                             int base, int need,
                                             int* outB, int* outCum) {
    int lane = threadIdx.x & 31;
    int hi = 4095 - 128 * lane;
    int s = 0;
    for (int k = 0; k < 128; k++) s += hist[hi - k];
    int incl = s;
#pragma unroll
    for (int off = 1; off < 32; off <<= 1) {
        int x = __shfl_up_sync(0xFFFFFFFFu, incl, off);
        if (lane >= off) incl += x;
    }
    int excl = incl - s;
    if (base + excl < need && base + incl >= need) {
        int c = base + excl;
        int b = hi;
        while (c + hist[b] < need) { c += hist[b]; b--; }
        *outB = b;
        *outCum = c;
    }
}

__global__ void findbin1_w(const int* __restrict__ hist1, int* B, int* cA, int need) {
    findbin_warp(hist1, 0, need, B, cA);
}

__global__ void hist2_kernel(const unsigned* __restrict__ skey, int n,
                             const int* __restrict__ B, int* __restrict__ hist2) {
    int i = blockIdx.x * blockDim.x + threadIdx.x;
    if (i >= n) return;
    unsigned s = skey[i];
    if ((int)(s >> 20) == *B) atomicAdd(&hist2[(s >> 8) & 0xFFF], 1);
}

__global__ void findbin2_w(const int* __restrict__ hist2, const int* B,
                           const int* cA, unsigned* T, int need) {
    __shared__ int outB;
    findbin_warp(hist2, *cA, need, &outB, (int*)0x0 + 0 == nullptr ? &outB : &outB);
    __syncwarp();
    if (threadIdx.x == 0)
        *T = (((unsigned)*B) << 20) | (((unsigned)outB) << 8);
}

__global__ void compact_kernel(const unsigned* __restrict__ skey, int n,
                               const unsigned* __restrict__ T,
                               unsigned long long* __restrict__ cand,
                               int* __restrict__ cnt) {
    int i = blockIdx.x * blockDim.x + threadIdx.x;
    if (i >= n) return;
    unsigned s = skey[i];
    if (s >= *T) {
        int p = atomicAdd(cnt, 1);
        if (p < 4096)
            cand[p] = (((unsigned long long)s) << 32) |
                      (unsigned long long)(0xFFFFFFFFu - (unsigned)i);
    }
}

__global__ void sortout_kernel(const unsigned long long* __restrict__ cand,
                               const int* __restrict__ cnt,
                               const float* __restrict__ h3,
                               float* __restrict__ out) {
    __shared__ unsigned long long sd[4096];
    int tid = threadIdx.x;  // 1024 threads
    int C = *cnt; if (C > 4096) C = 4096;
    int S = 1024; while (S < C) S <<= 1;   // adaptive size (C >= KTOP always)
    for (int i = tid; i < S; i += 1024) sd[i] = (i < C) ? cand[i] : 0ull;
    __syncthreads();
    for (int k = 2; k <= S; k <<= 1) {
        for (int j = k >> 1; j > 0; j >>= 1) {
            for (int t = tid; t < S; t += 1024) {
                int ixj = t ^ j;
                if (ixj > t) {
                    bool up = ((t & k) == 0);  // descending region
                    unsigned long long A = sd[t], Bv = sd[ixj];
                    bool sw = up ? (A < Bv) : (A > Bv);
                    if (sw) { sd[t] = Bv; sd[ixj] = A; }
                }
            }
            __syncthreads();
        }
    }
    for (int t = tid; t < KTOP * 32; t += 1024) {
        int r = t >> 5, c = t & 31;
        unsigned idx = 0xFFFFFFFFu - (unsigned)(sd[r] & 0xFFFFFFFFull);
        out[t] = h3[(size_t)idx * 32 + c];
    }
}

// ---------------------------------------------------------------------------
// Launch (prep branch overlapped with GEMM layer 1 via stream fork/join)
// ---------------------------------------------------------------------------

extern "C" void kernel_launch(void* const* d_in, const int* in_sizes, int n_in,
                              void* d_out, int out_size) {
    const float* x   = (const float*)d_in[0];
    const float* W1  = (const float*)d_in[1];
    const float* b1  = (const float*)d_in[2];
    const float* Wl1 = (const float*)d_in[3];
    const float* bl1 = (const float*)d_in[4];
    const float* W2  = (const float*)d_in[5];
    const float* b2  = (const float*)d_in[6];
    const float* Wl2 = (const float*)d_in[7];
    const float* bl2 = (const float*)d_in[8];
    const float* W3  = (const float*)d_in[9];
    const float* b3  = (const float*)d_in[10];
    const int*   ei  = (const int*)d_in[11];   // int32 per harness dtype map

    int n = in_sizes[0] / 64;
    int e = in_sizes[11] / 2;

    unsigned char* base = nullptr;
    cudaGetSymbolAddress((void**)&base, g_scratch);

    float* hw      = (float*)(base + OFF_HW);
    float* accA    = (float*)(base + OFF_ACCA);
    float* accB    = (float*)(base + OFF_ACCB);
    float* dinv    = (float*)(base + OFF_DINV);
    int*   deg     = (int*)(base + OFF_DEG);
    int*   fill    = (int*)(base + OFF_FILL);
    int*   rowptr  = (int*)(base + OFF_RP);
    int*   csrsrc  = (int*)(base + OFF_CSRS);
    float* csrnorm = (float*)(base + OFF_CSRN);
    unsigned* skey = (unsigned*)(base + OFF_SKEY);
    int*   hist1   = (int*)(base + OFF_H1);
    int*   hist2   = (int*)(base + OFF_H2);
    unsigned long long* cand = (unsigned long long*)(base + OFF_CAND);
    int*   bsum    = (int*)(base + OFF_BSUM);
    int*   bpre    = (int*)(base + OFF_BPRE);
    int*   misc    = (int*)(base + OFF_MISC);
    int*   cnt     = misc + 0;
    int*   Bbin    = misc + 1;
    int*   cA      = misc + 2;
    unsigned* T    = (unsigned*)(misc + 3);

    int ninit = (n > 4096) ? n : 4096;
    int nb = (n + 255) / 256;
    int gblocks = (n + 63) / 64;
    int ablocks = (n + 7) / 8;

    // Fork: prep (CSR build) on s2, GEMM layer 1 on the main stream.
    cudaStream_t s2;
    cudaStreamCreate(&s2);
    cudaEvent_t evFork, evJoin;
    cudaEventCreateWithFlags(&evFork, cudaEventDisableTiming);
    cudaEventCreateWithFlags(&evJoin, cudaEventDisableTiming);

    cudaEventRecord(evFork, 0);
    cudaStreamWaitEvent(s2, evFork, 0);

    // prep branch (s2)
    init_kernel<<<(ninit + 255) / 256, 256, 0, s2>>>(deg, fill, hist1, hist2, misc, n);
    deg_kernel<<<(e + 255) / 256, 256, 0, s2>>>(ei, e, deg, n);
    scanA<<<nb, 256, 0, s2>>>(deg, dinv, bsum, n);
    scanB<<<1, 256, 0, s2>>>(bsum, bpre, rowptr, nb, n);
    scanC<<<nb, 256, 0, s2>>>(deg, bpre, rowptr, n);
    scatter_kernel<<<(e + 255) / 256, 256, 0, s2>>>(ei, e, dinv, rowptr, fill, csrsrc, csrnorm, n);
    cudaEventRecord(evJoin, s2);

    // main stream: GEMM layer 1 (independent of CSR)
    gemm_fused<128, true><<<gblocks, 128>>>(x, W1, Wl1, b1, bl1, hw, accA, n);

    // join
    cudaStreamWaitEvent(0, evJoin, 0);

    agg64<<<ablocks, 256>>>(hw, accA, dinv, rowptr, csrsrc, csrnorm, accA, n);
    // Layer 2
    gemm_fused<128, true><<<gblocks, 128>>>(accA, W2, Wl2, b2, bl2, hw, accB, n);
    agg64<<<ablocks, 256>>>(hw, accB, dinv, rowptr, csrsrc, csrnorm, accB, n);
    // Layer 3 (no skip, 32 channels) + fused key/hist
    gemm_fused<32, false><<<gblocks, 128>>>(accB, W3, nullptr, nullptr, nullptr, hw, nullptr, n);
    agg32_key<<<ablocks, 256>>>(hw, b3, dinv, rowptr, csrsrc, csrnorm, accA, n, skey, hist1);

    // Top-K selection + ordered output
    findbin1_w<<<1, 32>>>(hist1, Bbin, cA, KTOP);
    hist2_kernel<<<(n + 255) / 256, 256>>>(skey, n, Bbin, hist2);
    findbin2_w<<<1, 32>>>(hist2, Bbin, cA, T, KTOP);
    compact_kernel<<<(n + 255) / 256, 256>>>(skey, n, T, cand, cnt);
    sortout_kernel<<<1, 1024>>>(cand, cnt, accA, (float*)d_out);

    cudaEventDestroy(evFork);
    cudaEventDestroy(evJoin);
    cudaStreamDestroy(s2);
}

// round 8
// speedup vs baseline: 1.8396x; 1.1061x over previous
#include <cuda_runtime.h>
#include <cuda_bf16.h>

// ---------------------------------------------------------------------------
// MultiLayerGnn: 3-layer GCN (+linear skips) + global_sort_pool top-K
// N=50000, E=800000, F_IN=H=64, C_OUT=32, K=1024
// edge_index delivered by the harness as int32 (2 rows of E).
// ---------------------------------------------------------------------------

#define NMAX 50000
#define EMAX 800000
#define KTOP 1024

static constexpr size_t AL(size_t x) { return (x + 255) & ~size_t(255); }

static constexpr size_t OFF_HW   = 0;
static constexpr size_t OFF_ACCA = AL(OFF_HW   + (size_t)NMAX * 64 * 4);
static constexpr size_t OFF_ACCB = AL(OFF_ACCA + (size_t)NMAX * 64 * 4);
static constexpr size_t OFF_DINV = AL(OFF_ACCB + (size_t)NMAX * 64 * 4);
static constexpr size_t OFF_DEG  = AL(OFF_DINV + (size_t)NMAX * 4);
static constexpr size_t OFF_FILL = AL(OFF_DEG  + (size_t)NMAX * 4);
static constexpr size_t OFF_RP   = AL(OFF_FILL + (size_t)NMAX * 4);
static constexpr size_t OFF_CSRS = AL(OFF_RP   + (size_t)(NMAX + 1) * 4);
static constexpr size_t OFF_CSRN = AL(OFF_CSRS + (size_t)EMAX * 4);
static constexpr size_t OFF_SKEY = AL(OFF_CSRN + (size_t)EMAX * 4);
static constexpr size_t OFF_H1   = AL(OFF_SKEY + (size_t)NMAX * 4);
static constexpr size_t OFF_BSUM = AL(OFF_H1   + 4096 * 4);
static constexpr size_t SCRATCH_TOTAL = AL(OFF_BSUM + 256 * 4);

__device__ __align__(256) unsigned char g_scratch[SCRATCH_TOTAL];

// ---------------------------------------------------------------------------
// f32x2 packed-FMA helpers (sm_100+; bit-identical per-lane to fmaf)
// ---------------------------------------------------------------------------

#define FMA2(d, a, b, c) \
    asm("fma.rn.f32x2 %0, %1, %2, %3;" : "=l"(d) : "l"(a), "l"(b), "l"(c))

__device__ __forceinline__ unsigned long long dup2(float x) {
    unsigned long long r; unsigned u = __float_as_uint(x);
    asm("mov.b64 %0, {%1, %2};" : "=l"(r) : "r"(u), "r"(u));
    return r;
}

__device__ __forceinline__ float2 unpk2(unsigned long long v) {
    unsigned lo, hi;
    asm("mov.b64 {%0, %1}, %2;" : "=r"(lo), "=r"(hi) : "l"(v));
    return make_float2(__uint_as_float(lo), __uint_as_float(hi));
}

// ---------------------------------------------------------------------------
// Prep kernels (deg = edge-only count; self-loop handled via d+1)
// ---------------------------------------------------------------------------

__global__ void init_kernel(int* deg, int* fill, int* hist1, int n) {
    int i = blockIdx.x * blockDim.x + threadIdx.x;
    if (i < n) { deg[i] = 0; fill[i] = 0; }
    if (i < 4096) hist1[i] = 0;
}

__global__ void deg_kernel(const int* __restrict__ ei, int e,
                           int* __restrict__ deg, int n) {
    int i = blockIdx.x * blockDim.x + threadIdx.x;
    if (i >= e) return;
    unsigned d = (unsigned)ei[e + i];
    if (d < (unsigned)n) atomicAdd(&deg[d], 1);
}

// Phase A: per-block sums of deg + fused dinv (= rsqrt(deg+1))
__global__ void scanA(const int* __restrict__ deg, float* __restrict__ dinv,
                      int* __restrict__ bsum, int n) {
    __shared__ int sh[256];
    int t = threadIdx.x;
    int i = blockIdx.x * 256 + t;
    int v = 0;
    if (i < n) {
        int d = deg[i];
        dinv[i] = rsqrtf((float)(d + 1));
        v = d;
    }
    sh[t] = v;
    __syncthreads();
    for (int off = 128; off > 0; off >>= 1) {
        if (t < off) sh[t] += sh[t + off];
        __syncthreads();
    }
    if (t == 0) bsum[blockIdx.x] = sh[0];
}

// Phase C (fused B): each block computes its own prefix from bsum, then local scan.
__global__ void scanC2(const int* __restrict__ deg, const int* __restrict__ bsum,
                       int* __restrict__ rowptr, int nb, int n) {
    __shared__ int sh[256];
    __shared__ int pref;
    int t = threadIdx.x, bid = blockIdx.x;
    sh[t] = (t < bid) ? bsum[t] : 0;     // nb <= 256
    __syncthreads();
    for (int off = 128; off > 0; off >>= 1) {
        if (t < off) sh[t] += sh[t + off];
        __syncthreads();
    }
    if (t == 0) pref = sh[0];
    __syncthreads();
    int i = bid * 256 + t;
    int v = (i < n) ? deg[i] : 0;
    sh[t] = v;
    __syncthreads();
    for (int off = 1; off < 256; off <<= 1) {
        int x = (t >= off) ? sh[t - off] : 0;
        __syncthreads();
        sh[t] += x;
        __syncthreads();
    }
    if (i < n) rowptr[i] = pref + sh[t] - v;
    if (bid == nb - 1 && t == 0) rowptr[n] = pref + bsum[bid];
}

__global__ void scatter_kernel(const int* __restrict__ ei, int e,
                               const float* __restrict__ dinv,
                               const int* __restrict__ rowptr,
                               int* __restrict__ fill,
                               int* __restrict__ csrsrc,
                               float* __restrict__ csrnorm, int n) {
    int i = blockIdx.x * blockDim.x + threadIdx.x;
    if (i >= e) return;
    unsigned s = (unsigned)ei[i];
    unsigned d = (unsigned)ei[e + i];
    if (s >= (unsigned)n || d >= (unsigned)n) return;
    int p = atomicAdd(&fill[d], 1);
    int idx = rowptr[d] + p;
    csrsrc[idx] = (int)s;
    csrnorm[idx] = dinv[s] * dinv[d];
}

// ---------------------------------------------------------------------------
// Fused GEMM via packed f32x2 FMA: hw = h @ W ; (skip) accout = b + 0.5*(h@Wl+bl)
// ---------------------------------------------------------------------------

template <int CW, bool SKIP>
__global__ __launch_bounds__(128) void gemm_fused(
    const float* __restrict__ hin,
    const float* __restrict__ W, const float* __restrict__ Wl,
    const float* __restrict__ b, const float* __restrict__ bl,
    float* __restrict__ hw, float* __restrict__ accout, int n) {
    constexpr int HOUT = SKIP ? CW / 2 : CW;
    constexpr int CT = CW / 16;
    constexpr int CT2 = CT / 2;
    __shared__ float As[64][64];   // As[k][row] (transposed)
    __shared__ float Ws[64][CW];

    int tid = threadIdx.x;
    int base = blockIdx.x * 64;

    for (int f = tid; f < 64 * 16; f += 128) {
        int row = f >> 4, c4 = f & 15;
        float4 v = make_float4(0.f, 0.f, 0.f, 0.f);
        int gr = base + row;
        if (gr < n) v = ((const float4*)hin)[(size_t)gr * 16 + c4];
        int k = c4 * 4;
        As[k + 0][row] = v.x;
        As[k + 1][row] = v.y;
        As[k + 2][row] = v.z;
        As[k + 3][row] = v.w;
    }
    for (int f = tid; f < 64 * CW; f += 128) {
        int k = f / CW, j = f % CW;
        float w;
        if (SKIP) w = (j < HOUT) ? W[k * HOUT + j] : Wl[k * HOUT + (j - HOUT)];
        else      w = W[k * CW + j];
        Ws[k][j] = w;
    }
    __syncthreads();

    int tcol = tid & 15, trow = tid >> 4;
    unsigned long long acc2[8][CT2];
#pragma unroll
    for (int i = 0; i < 8; i++)
#pragma unroll
        for (int c = 0; c < CT2; c++) acc2[i][c] = 0ull;

#pragma unroll 4
    for (int k = 0; k < 64; k++) {
        float4 a0 = *(const float4*)&As[k][trow * 8];
        float4 a1 = *(const float4*)&As[k][trow * 8 + 4];
        float a[8] = {a0.x, a0.y, a0.z, a0.w, a1.x, a1.y, a1.z, a1.w};
        unsigned long long w2[CT2];
#pragma unroll
        for (int c = 0; c < CT2; c++)
            w2[c] = *(const unsigned long long*)&Ws[k][tcol * CT + 2 * c];
#pragma unroll
        for (int i = 0; i < 8; i++) {
            unsigned long long ad = dup2(a[i]);
#pragma unroll
            for (int c = 0; c < CT2; c++)
                FMA2(acc2[i][c], ad, w2[c], acc2[i][c]);
        }
    }

#pragma unroll
    for (int i = 0; i < 8; i++) {
        int gr = base + trow * 8 + i;
        if (gr >= n) continue;
#pragma unroll
        for (int c = 0; c < CT2; c++) {
            int col = tcol * CT + 2 * c;
            float2 p = unpk2(acc2[i][c]);
            if (SKIP) {
                if (col < HOUT) {       // pair never straddles HOUT (col even, HOUT=64)
                    *(float2*)&hw[(size_t)gr * HOUT + col] = p;
                } else {
                    int j = col - HOUT;
                    accout[(size_t)gr * HOUT + j]     = b[j]     + 0.5f * (p.x + bl[j]);
                    accout[(size_t)gr * HOUT + j + 1] = b[j + 1] + 0.5f * (p.y + bl[j + 1]);
                }
            } else {
                *(float2*)&hw[(size_t)gr * CW + col] = p;
            }
        }
    }
}

// ---------------------------------------------------------------------------
// Aggregation: warp per node, CSR gather.
// ---------------------------------------------------------------------------

__global__ void agg64(const float* __restrict__ hw, const float* accin,
                      const float* __restrict__ dinv,
                      const int* __restrict__ rowptr,
                      const int* __restrict__ csrsrc,
                      const float* __restrict__ csrnorm,
                      float* out, int n) {
    int warp = (blockIdx.x * blockDim.x + threadIdx.x) >> 5;
    int lane = threadIdx.x & 31;
    if (warp >= n) return;
    const float2* hp = (const float2*)hw;
    float di = dinv[warp];
    float di2 = di * di;
    float2 s2 = hp[(size_t)warp * 32 + lane];
    float ax = s2.x * di2, ay = s2.y * di2;
    int e = rowptr[warp], e1 = rowptr[warp + 1];
    for (; e + 3 < e1; e += 4) {
        int s0 = csrsrc[e],      s1 = csrsrc[e + 1];
        int s2i = csrsrc[e + 2], s3 = csrsrc[e + 3];
        float n0 = csrnorm[e],     n1 = csrnorm[e + 1];
        float n2 = csrnorm[e + 2], n3 = csrnorm[e + 3];
        float2 v0 = hp[(size_t)s0 * 32 + lane];
        float2 v1 = hp[(size_t)s1 * 32 + lane];
        float2 v2 = hp[(size_t)s2i * 32 + lane];
        float2 v3 = hp[(size_t)s3 * 32 + lane];
        ax = fmaf(v0.x, n0, ax); ay = fmaf(v0.y, n0, ay);
        ax = fmaf(v1.x, n1, ax); ay = fmaf(v1.y, n1, ay);
        ax = fmaf(v2.x, n2, ax); ay = fmaf(v2.y, n2, ay);
        ax = fmaf(v3.x, n3, ax); ay = fmaf(v3.y, n3, ay);
    }
    for (; e < e1; e++) {
        int sa = csrsrc[e]; float na = csrnorm[e];
        float2 va = hp[(size_t)sa * 32 + lane];
        ax = fmaf(va.x, na, ax); ay = fmaf(va.y, na, ay);
    }
    float2 bse = ((const float2*)accin)[(size_t)warp * 32 + lane];
    float rx = fmaxf(bse.x + ax, 0.f);
    float ry = fmaxf(bse.y + ay, 0.f);
    ((float2*)out)[(size_t)warp * 32 + lane] = make_float2(rx, ry);
}

// Layer-3 agg (32 ch) with fused sort-key + hist1 build (lane 31 owns ch 31).
__global__ void agg32_key(const float* __restrict__ hw, const float* __restrict__ bias,
                          const float* __restrict__ dinv,
                          const int* __restrict__ rowptr,
                          const int* __restrict__ csrsrc,
                          const float* __restrict__ csrnorm,
                          float* __restrict__ out, int n,
                          unsigned* __restrict__ skey, int* __restrict__ hist1) {
    int warp = (blockIdx.x * blockDim.x + threadIdx.x) >> 5;
    int lane = threadIdx.x & 31;
    if (warp >= n) return;
    float di = dinv[warp];
    float di2 = di * di;
    float acc = hw[(size_t)warp * 32 + lane] * di2;
    int e = rowptr[warp], e1 = rowptr[warp + 1];
    for (; e + 3 < e1; e += 4) {
        int s0 = csrsrc[e],     s1 = csrsrc[e + 1];
        int s2 = csrsrc[e + 2], s3 = csrsrc[e + 3];
        float n0 = csrnorm[e],     n1 = csrnorm[e + 1];
        float n2 = csrnorm[e + 2], n3 = csrnorm[e + 3];
        float v0 = hw[(size_t)s0 * 32 + lane];
        float v1 = hw[(size_t)s1 * 32 + lane];
        float v2 = hw[(size_t)s2 * 32 + lane];
        float v3 = hw[(size_t)s3 * 32 + lane];
        acc = fmaf(v0, n0, acc); acc = fmaf(v1, n1, acc);
        acc = fmaf(v2, n2, acc); acc = fmaf(v3, n3, acc);
    }
    for (; e < e1; e++) {
        acc = fmaf(hw[(size_t)csrsrc[e] * 32 + lane], csrnorm[e], acc);
    }
    float v = acc + bias[lane];
    out[(size_t)warp * 32 + lane] = v;
    if (lane == 31) {
        unsigned u = __float_as_uint(v);
        unsigned s = (u & 0x80000000u) ? ~u : (u | 0x80000000u);
        skey[warp] = s;
        atomicAdd(&hist1[s >> 20], 1);
    }
}

// ---------------------------------------------------------------------------
// Merged top-K finisher: findbin1 + hist2 + findbin2 + compact + sort + gather
// Single block, 1024 threads. Same semantics as the proven multi-kernel path.
// ---------------------------------------------------------------------------

__device__ __forceinline__ void findbin_warp(const int* __restrict__ hist,
                                             int base, int need,
                                             int* outB, int* outCum) {
    int lane = threadIdx.x & 31;
    int hi = 4095 - 128 * lane;
    int s = 0;
    for (int k = 0; k < 128; k++) s += hist[hi - k];
    int incl = s;
#pragma unroll
    for (int off = 1; off < 32; off <<= 1) {
        int x = __shfl_up_sync(0xFFFFFFFFu, incl, off);
        if (lane >= off) incl += x;
    }
    int excl = incl - s;
    if (base + excl < need && base + incl >= need) {
        int c = base + excl;
        int b = hi;
        while (c + hist[b] < need) { c += hist[b]; b--; }
        *outB = b;
        *outCum = c;
    }
}

__global__ __launch_bounds__(1024) void select_topk(
    const unsigned* __restrict__ skey, int n,
    const int* __restrict__ hist1,
    const float* __restrict__ h3, float* __restrict__ out) {
    __shared__ unsigned long long sd[4096];
    __shared__ int B1, C1, B2, C2, scnt;
    __shared__ unsigned Tsh;
    int* hist2 = (int*)sd;   // alias: hist2 used (phases 2-3) before sd (phase 4+)
    int tid = threadIdx.x;

    if (tid == 0) scnt = 0;
    for (int i = tid; i < 4096; i += 1024) hist2[i] = 0;
    __syncthreads();

    // Phase 1: level-1 bin
    if (tid < 32) findbin_warp(hist1, 0, KTOP, &B1, &C1);
    __syncthreads();
    int b1 = B1, c1 = C1;

    // Phase 2: level-2 histogram (smem)
    for (int i = tid; i < n; i += 1024) {
        unsigned s = skey[i];
        if ((int)(s >> 20) == b1) atomicAdd(&hist2[(s >> 8) & 0xFFF], 1);
    }
    __syncthreads();

    // Phase 3: level-2 bin -> threshold
    if (tid < 32) findbin_warp(hist2, c1, KTOP, &B2, &C2);
    __syncthreads();
    if (tid == 0) Tsh = (((unsigned)b1) << 20) | (((unsigned)B2) << 8);
    __syncthreads();
    unsigned T = Tsh;
    __syncthreads();   // hist2 reads done before sd overwrite

    // Phase 4: compact candidates into sd
    for (int i = tid; i < n; i += 1024) {
        unsigned s = skey[i];
        if (s >= T) {
            int p = atomicAdd(&scnt, 1);
            if (p < 4096)
                sd[p] = (((unsigned long long)s) << 32) |
                        (unsigned long long)(0xFFFFFFFFu - (unsigned)i);
        }
    }
    __syncthreads();

    // Phase 5: adaptive bitonic sort (descending) + gather output
    int C = scnt; if (C > 4096) C = 4096;
    int S = 1024; while (S < C) S <<= 1;
    for (int i = tid; i < S; i += 1024) if (i >= C) sd[i] = 0ull;
    __syncthreads();
    for (int k = 2; k <= S; k <<= 1) {
        for (int j = k >> 1; j > 0; j >>= 1) {
            for (int t = tid; t < S; t += 1024) {
                int ixj = t ^ j;
                if (ixj > t) {
                    bool up = ((t & k) == 0);
                    unsigned long long A = sd[t], Bv = sd[ixj];
                    bool sw = up ? (A < Bv) : (A > Bv);
                    if (sw) { sd[t] = Bv; sd[ixj] = A; }
                }
            }
            __syncthreads();
        }
    }
    for (int t = tid; t < KTOP * 32; t += 1024) {
        int r = t >> 5, c = t & 31;
        unsigned idx = 0xFFFFFFFFu - (unsigned)(sd[r] & 0xFFFFFFFFull);
        out[t] = h3[(size_t)idx * 32 + c];
    }
}

// ---------------------------------------------------------------------------
// Launch (prep branch overlapped with GEMM layer 1 via stream fork/join)
// ---------------------------------------------------------------------------

extern "C" void kernel_launch(void* const* d_in, const int* in_sizes, int n_in,
                              void* d_out, int out_size) {
    const float* x   = (const float*)d_in[0];
    const float* W1  = (const float*)d_in[1];
    const float* b1  = (const float*)d_in[2];
    const float* Wl1 = (const float*)d_in[3];
    const float* bl1 = (const float*)d_in[4];
    const float* W2  = (const float*)d_in[5];
    const float* b2  = (const float*)d_in[6];
    const float* Wl2 = (const float*)d_in[7];
    const float* bl2 = (const float*)d_in[8];
    const float* W3  = (const float*)d_in[9];
    const float* b3  = (const float*)d_in[10];
    const int*   ei  = (const int*)d_in[11];   // int32 per harness dtype map

    int n = in_sizes[0] / 64;
    int e = in_sizes[11] / 2;

    unsigned char* base = nullptr;
    cudaGetSymbolAddress((void**)&base, g_scratch);

    float* hw      = (float*)(base + OFF_HW);
    float* accA    = (float*)(base + OFF_ACCA);
    float* accB    = (float*)(base + OFF_ACCB);
    float* dinv    = (float*)(base + OFF_DINV);
    int*   deg     = (int*)(base + OFF_DEG);
    int*   fill    = (int*)(base + OFF_FILL);
    int*   rowptr  = (int*)(base + OFF_RP);
    int*   csrsrc  = (int*)(base + OFF_CSRS);
    float* csrnorm = (float*)(base + OFF_CSRN);
    unsigned* skey = (unsigned*)(base + OFF_SKEY);
    int*   hist1   = (int*)(base + OFF_H1);
    int*   bsum    = (int*)(base + OFF_BSUM);

    int ninit = (n > 4096) ? n : 4096;
    int nb = (n + 255) / 256;
    int gblocks = (n + 63) / 64;
    int ablocks = (n + 7) / 8;

    // Fork: prep (CSR build) on s2, GEMM layer 1 on the main stream.
    cudaStream_t s2;
    cudaStreamCreate(&s2);
    cudaEvent_t evFork, evJoin;
    cudaEventCreateWithFlags(&evFork, cudaEventDisableTiming);
    cudaEventCreateWithFlags(&evJoin, cudaEventDisableTiming);

    cudaEventRecord(evFork, 0);
    cudaStreamWaitEvent(s2, evFork, 0);

    // prep branch (s2)
    init_kernel<<<(ninit + 255) / 256, 256, 0, s2>>>(deg, fill, hist1, n);
    deg_kernel<<<(e + 255) / 256, 256, 0, s2>>>(ei, e, deg, n);
    scanA<<<nb, 256, 0, s2>>>(deg, dinv, bsum, n);
    scanC2<<<nb, 256, 0, s2>>>(deg, bsum, rowptr, nb, n);
    scatter_kernel<<<(e + 255) / 256, 256, 0, s2>>>(ei, e, dinv, rowptr, fill, csrsrc, csrnorm, n);
    cudaEventRecord(evJoin, s2);

    // main stream: GEMM layer 1 (independent of CSR)
    gemm_fused<128, true><<<gblocks, 128>>>(x, W1, Wl1, b1, bl1, hw, accA, n);

    // join
    cudaStreamWaitEvent(0, evJoin, 0);

    agg64<<<ablocks, 256>>>(hw, accA, dinv, rowptr, csrsrc, csrnorm, accA, n);
    // Layer 2
    gemm_fused<128, true><<<gblocks, 128>>>(accA, W2, Wl2, b2, bl2, hw, accB, n);
    agg64<<<ablocks, 256>>>(hw, accB, dinv, rowptr, csrsrc, csrnorm, accB, n);
    // Layer 3 (no skip, 32 channels) + fused key/hist
    gemm_fused<32, false><<<gblocks, 128>>>(accB, W3, nullptr, nullptr, nullptr, hw, nullptr, n);
    agg32_key<<<ablocks, 256>>>(hw, b3, dinv, rowptr, csrsrc, csrnorm, accA, n, skey, hist1);

    // Merged top-K finisher
    select_topk<<<1, 1024>>>(skey, n, hist1, accA, (float*)d_out);

    cudaEventDestroy(evFork);
    cudaEventDestroy(evJoin);
    cudaStreamDestroy(s2);
}